// round 14
// baseline (speedup 1.0000x reference)
#include <cuda_runtime.h>

#define B_  64
#define L_  200
#define NS_ 1000
#define D_  128
#define M_  50
#define BL_ (B_*L_)
#define WSTR 64   // padded w-row stride (slots 50..63 zero)
#define NBLK 128

// -------- scratch (device globals; no allocation allowed) --------
__device__ float g_eWT[D_*D_];        // e_W transposed [k][d]
__device__ float g_aWT[D_*D_];        // a_W transposed
__device__ float g_frT[D_*D_];        // read-half of f_W transposed [k][d]
__device__ float g_fkT[D_*D_];        // k-half of f_W transposed
__device__ float g_wtab[1024*WSTR];   // softmax weights per skill (padded)
__device__ float g_etab[2048*D_];     // sigmoid erase per x (rows>=2000 junk)
__device__ float g_atab[2048*D_];     // tanh add per x
__device__ float g_kftab[1024*D_];    // k_emb[s] @ f_Wk^T + f_b
__device__ float g_read[BL_*D_];      // read vectors

// -------- grid barrier state (sense-reversing; survives graph replays) ----
__device__ unsigned g_bcnt[3];
__device__ volatile unsigned g_bsense[3];

__device__ __forceinline__ void gbar(int i){
    __threadfence();
    __syncthreads();
    if (threadIdx.x == 0) {
        unsigned s = g_bsense[i];
        unsigned old = atomicAdd(&g_bcnt[i], 1u);
        if (old == NBLK - 1u) {
            g_bcnt[i] = 0u;
            __threadfence();
            g_bsense[i] = s ^ 1u;
        } else {
            while (g_bsense[i] == s) __nanosleep(32);
        }
    }
    __syncthreads();
    __threadfence();
}

__device__ __forceinline__ float fsigmoid(float x){ return 1.f/(1.f+__expf(-x)); }
__device__ __forceinline__ float ftanh(float x){ float y; asm("tanh.approx.f32 %0, %1;":"=f"(y):"f"(x)); return y; }
__device__ __forceinline__ unsigned tf32r(float x){
    unsigned r; asm("cvt.rna.tf32.f32 %0, %1;" : "=r"(r) : "f"(x)); return r;
}
__device__ __forceinline__ void mma8(float* c,
        unsigned a0, unsigned a1, unsigned a2, unsigned a3,
        unsigned b0, unsigned b1){
    asm("mma.sync.aligned.m16n8k8.row.col.f32.tf32.tf32.f32 "
        "{%0,%1,%2,%3}, {%4,%5,%6,%7}, {%8,%9}, {%0,%1,%2,%3};"
        : "+f"(c[0]), "+f"(c[1]), "+f"(c[2]), "+f"(c[3])
        : "r"(a0), "r"(a1), "r"(a2), "r"(a3), "r"(b0), "r"(b1));
}

// =====================================================================
// Fused persistent kernel: 128 blocks x 512 threads, 150KB dyn smem
// (1 block/SM, all co-resident => global spin barrier is safe).
//  phase 0: weight transposes        (blocks 0..63, one 32x32 tile each)
//  phase 1: tables e/a/kf (tf32 mma) + w (softmax)   (blocks 0..95)
//  phase 2: scan, block = (b, dhalf)                 (all 128)
//  phase 3: output tf32 GEMM + head                  (blocks 0..99)
// =====================================================================
extern "C" __global__ void __launch_bounds__(512)
k_all(const int* __restrict__ skills, const int* __restrict__ responses,
      const float* __restrict__ k_emb, const float* __restrict__ v_emb,
      const float* __restrict__ Mk, const float* __restrict__ Mv0,
      const float* __restrict__ e_W, const float* __restrict__ e_b,
      const float* __restrict__ a_W, const float* __restrict__ a_b,
      const float* __restrict__ f_W, const float* __restrict__ f_b,
      const float* __restrict__ p_W, const float* __restrict__ p_b,
      float* __restrict__ out)
{
    extern __shared__ float sm[];
    const int tid = threadIdx.x;
    const int bid = blockIdx.x;

    // ---------------- phase 0: weight transposes ----------------
    if (bid < 64) {
        __shared__ float tile[32][33];
        const int m  = bid >> 4;           // matrix 0..3
        const int tb = bid & 15;           // tile 0..15
        const int d0 = (tb & 3) * 32;
        const int k0 = (tb >> 2) * 32;
        const int c  = tid & 31;
        const int rb = tid >> 5;           // 0..15

        const float* src; int stride, off; float* dst;
        if      (m == 0) { src = e_W; stride = D_;   off = 0;   dst = g_eWT; }
        else if (m == 1) { src = a_W; stride = D_;   off = 0;   dst = g_aWT; }
        else if (m == 2) { src = f_W; stride = 2*D_; off = 0;   dst = g_frT; }
        else             { src = f_W; stride = 2*D_; off = D_;  dst = g_fkT; }

        #pragma unroll
        for (int p = 0; p < 2; p++) {
            int r = rb + p*16;
            tile[r][c] = src[(size_t)(d0 + r)*stride + off + k0 + c];
        }
        __syncthreads();
        #pragma unroll
        for (int p = 0; p < 2; p++) {
            int r = rb + p*16;
            dst[(size_t)(k0 + r)*D_ + d0 + c] = tile[c][r];
        }
    }
    gbar(0);

    // ---------------- phase 1: tables ----------------
    if (bid < 80) {
        // e/a/kf tables: tf32 mma GEMM, 64 rows/block
        float* hA = sm;                  // 64*132
        float* hB = sm + 64*132;         // 128*136
        const int type  = (bid < 32) ? 0 : (bid < 64) ? 1 : 2;
        const int rbase = (type == 0 ? bid : type == 1 ? bid - 32 : bid - 64) * 64;
        const float* WT = (type == 0) ? g_eWT : (type == 1) ? g_aWT : g_fkT;
        const float* xs = (type == 2) ? k_emb : v_emb;
        const float* bv = (type == 0) ? e_b : (type == 1) ? a_b : f_b;
        const int rmax  = (type == 2) ? NS_ - 1 : 2*NS_ - 1;

        {
            const float4* xs4 = (const float4*)xs;
            #pragma unroll
            for (int i = 0; i < 4; i++) {
                int u = tid + i*512;
                int r = u >> 5, c = u & 31;
                int rr = min(rbase + r, rmax);
                float4 v = __ldg(&xs4[(size_t)rr*32 + c]);
                v.x = __uint_as_float(tf32r(v.x)); v.y = __uint_as_float(tf32r(v.y));
                v.z = __uint_as_float(tf32r(v.z)); v.w = __uint_as_float(tf32r(v.w));
                *(float4*)&hA[r*132 + c*4] = v;
            }
        }
        {
            const float4* wt4 = (const float4*)WT;
            #pragma unroll
            for (int i = 0; i < 8; i++) {
                int u = tid + i*512;
                int k = u >> 5, c = u & 31;
                float4 v = __ldg(&wt4[u]);
                v.x = __uint_as_float(tf32r(v.x)); v.y = __uint_as_float(tf32r(v.y));
                v.z = __uint_as_float(tf32r(v.z)); v.w = __uint_as_float(tf32r(v.w));
                *(float4*)&hB[k*136 + c*4] = v;
            }
        }
        __syncthreads();

        const int wid = tid >> 5, lane = tid & 31;
        const int g = lane >> 2, t = lane & 3;
        const int stripe = wid >> 2, q = wid & 3;
        const int rw = stripe * 16;

        float acc[4][4];
        #pragma unroll
        for (int n = 0; n < 4; n++)
            #pragma unroll
            for (int j = 0; j < 4; j++) acc[n][j] = 0.f;

        const float* Abase = hA + (rw + g)*132 + t;
        #pragma unroll 4
        for (int kk = 0; kk < 16; kk++) {
            const int k0 = kk*8;
            unsigned a0 = __float_as_uint(Abase[k0]);
            unsigned a1 = __float_as_uint(Abase[k0 + 8*132]);
            unsigned a2 = __float_as_uint(Abase[k0 + 4]);
            unsigned a3 = __float_as_uint(Abase[k0 + 8*132 + 4]);
            const float* B0 = hB + (k0 + t)*136 + g + q*32;
            const float* B1 = B0 + 4*136;
            #pragma unroll
            for (int n = 0; n < 4; n++) {
                unsigned b0 = __float_as_uint(B0[n*8]);
                unsigned b1 = __float_as_uint(B1[n*8]);
                mma8(acc[n], a0, a1, a2, a3, b0, b1);
            }
        }

        const int rlo = rbase + rw + g, rhi = rlo + 8;
        #pragma unroll
        for (int n = 0; n < 4; n++) {
            int c = q*32 + n*8 + 2*t;
            float2 bb = *(const float2*)&bv[c];
            float x0 = acc[n][0] + bb.x, x1 = acc[n][1] + bb.y;
            float y0 = acc[n][2] + bb.x, y1 = acc[n][3] + bb.y;
            float2 lo, hi;
            if (type == 0) {
                lo.x = fsigmoid(x0); lo.y = fsigmoid(x1);
                hi.x = fsigmoid(y0); hi.y = fsigmoid(y1);
                *(float2*)&g_etab[(size_t)rlo*D_ + c] = lo;
                *(float2*)&g_etab[(size_t)rhi*D_ + c] = hi;
            } else if (type == 1) {
                lo.x = ftanh(x0); lo.y = ftanh(x1);
                hi.x = ftanh(y0); hi.y = ftanh(y1);
                *(float2*)&g_atab[(size_t)rlo*D_ + c] = lo;
                *(float2*)&g_atab[(size_t)rhi*D_ + c] = hi;
            } else {
                lo.x = x0; lo.y = x1; hi.x = y0; hi.y = y1;
                *(float2*)&g_kftab[(size_t)rlo*D_ + c] = lo;
                *(float2*)&g_kftab[(size_t)rhi*D_ + c] = hi;
            }
        }
    } else if (bid < 96) {
        // w (softmax) table, 64 rows, FFMA
        float* sx  = sm;                 // 64*128
        float* MkT = sm + 64*D_;         // 128*65
        const int rbase = (bid - 80) * 64;
        const int tx = tid & 31, ty = tid >> 5;
        const int r0 = ty * 4;

        for (int i = tid; i < M_*D_; i += 512) {
            int m = i >> 7, k = i & 127;
            MkT[k*65 + m] = Mk[i];
        }
        for (int i = tid; i < D_*14; i += 512) {
            int k = i / 14, m = 50 + (i % 14);
            MkT[k*65 + m] = 0.f;
        }
        {
            float4* s4 = (float4*)sx;
            const float4* ke4 = (const float4*)k_emb;
            #pragma unroll
            for (int i = 0; i < 4; i++) {
                int u = tid + i*512;
                int r = u >> 5, cc = u & 31;
                int rr = min(rbase + r, NS_ - 1);
                s4[u] = __ldg(&ke4[(size_t)rr*32 + cc]);
            }
        }
        __syncthreads();

        const int m0 = tx, m1 = tx + 32;
        float a0[4] = {}, a1[4] = {};
        const float4* s4 = (const float4*)sx;
        #pragma unroll 4
        for (int k4 = 0; k4 < 32; k4++) {
            float4 kr[4];
            #pragma unroll
            for (int i = 0; i < 4; i++) kr[i] = s4[(r0+i)*32 + k4];
            #pragma unroll
            for (int s = 0; s < 4; s++) {
                int k = 4*k4 + s;
                float mv0 = MkT[k*65 + m0];
                float mv1 = MkT[k*65 + m1];
                #pragma unroll
                for (int i = 0; i < 4; i++) {
                    float kv = ((const float*)&kr[i])[s];
                    a0[i] = fmaf(kv, mv0, a0[i]);
                    a1[i] = fmaf(kv, mv1, a1[i]);
                }
            }
        }
        #pragma unroll
        for (int i = 0; i < 4; i++) {
            float v0 = a0[i];
            float v1 = (m1 < M_) ? a1[i] : -1e30f;
            float mx = fmaxf(v0, v1);
            #pragma unroll
            for (int o = 16; o >= 1; o >>= 1) mx = fmaxf(mx, __shfl_xor_sync(0xffffffffu, mx, o));
            float e0 = __expf(v0 - mx);
            float e1 = (m1 < M_) ? __expf(v1 - mx) : 0.f;
            float s = e0 + e1;
            #pragma unroll
            for (int o = 16; o >= 1; o >>= 1) s += __shfl_xor_sync(0xffffffffu, s, o);
            float inv = __frcp_rn(s);
            int row = rbase + r0 + i;
            g_wtab[row*WSTR + m0] = e0 * inv;
            g_wtab[row*WSTR + m1] = e1 * inv;   // zero in pad region
        }
    }
    gbar(1);

    // ---------------- phase 2: scan ----------------
    {
        float* s_w = sm;               // L*64
        float* s_e = sm + L_*64;
        float* s_a = sm + 2*L_*64;
        __shared__ int s_x[L_], s_skb[L_];

        const int b     = bid >> 1;
        const int dhalf = bid & 1;

        for (int t = tid; t < L_; t += 512) {
            int sk = skills[b*L_ + t];
            int r  = responses[b*L_ + t];
            int mr = (r > -1) ? r : 0;
            s_skb[t] = sk;
            s_x[t]   = sk + NS_ * mr;
        }
        __syncthreads();

        {
            float4* sw4 = (float4*)s_w;
            float4* se4 = (float4*)s_e;
            float4* sa4 = (float4*)s_a;
            const float4* wt4 = (const float4*)g_wtab;
            const float4* et4 = (const float4*)g_etab;
            const float4* at4 = (const float4*)g_atab;
            const int dbase4 = dhalf * 16;
            for (int u = tid; u < L_*16; u += 512) {
                int t = u >> 4, c = u & 15;
                int xx = s_x[t], kk = s_skb[t];
                sw4[u] = __ldg(&wt4[kk*16 + c]);
                se4[u] = __ldg(&et4[(size_t)xx*32 + dbase4 + c]);
                sa4[u] = __ldg(&at4[(size_t)xx*32 + dbase4 + c]);
            }
        }
        __syncthreads();

        const int mg  = tid & 7;
        const int dl  = tid >> 3;
        const int d   = dhalf * 64 + dl;

        float mv[7];
        #pragma unroll
        for (int j = 0; j < 7; j++) {
            int m = mg + 8*j;
            mv[j] = (m < M_) ? Mv0[m*D_ + d] : 0.f;
        }

        float* rp = g_read + (size_t)b*L_*D_ + d;

        #pragma unroll 2
        for (int t = 0; t < L_; t++) {
            float ev = s_e[t*64 + dl];
            float av = s_a[t*64 + dl];
            const float* wrow = &s_w[t*64 + mg];

            float rda = 0.f, rdb = 0.f;
            #pragma unroll
            for (int j = 0; j < 7; j++) {
                float w = wrow[8*j];
                float r_ = fmaf(w, mv[j], 0.f);
                if (j & 1) rdb += r_; else rda += r_;
                float g = fmaf(-ev, mv[j], av);      // a - e*mv
                mv[j] = fmaf(w, g, mv[j]);           // mv += w*(a - e*mv)
            }
            float rd = rda + rdb;
            rd += __shfl_xor_sync(0xffffffffu, rd, 1);
            rd += __shfl_xor_sync(0xffffffffu, rd, 2);
            rd += __shfl_xor_sync(0xffffffffu, rd, 4);
            if (mg == 0) rp[t*D_] = rd;
        }
    }
    gbar(2);

    // ---------------- phase 3: output GEMM + head ----------------
    if (bid < 100) {
        float* hA   = sm;                       // 128*132 (A tf32, later kf tile)
        float* hB   = sm + 128*132;             // 128*136
        float* spw  = sm + 128*132 + 128*136;   // 128 (p_W)
        float* sred = spw + 128;                // 256
        __shared__ int s_sk[128];

        const int row0 = bid * 128;

        if (tid < 128) { s_sk[tid] = skills[row0 + tid]; spw[tid] = p_W[tid]; }
        {
            const float4* rd4 = (const float4*)g_read;
            #pragma unroll
            for (int i = 0; i < 8; i++) {
                int u = tid + i*512;
                int r = u >> 5, c = u & 31;
                float4 v = __ldg(&rd4[(size_t)row0*32 + u]);
                v.x = __uint_as_float(tf32r(v.x)); v.y = __uint_as_float(tf32r(v.y));
                v.z = __uint_as_float(tf32r(v.z)); v.w = __uint_as_float(tf32r(v.w));
                *(float4*)&hA[r*132 + c*4] = v;
            }
        }
        {
            const float4* wt4 = (const float4*)g_frT;
            #pragma unroll
            for (int i = 0; i < 8; i++) {
                int u = tid + i*512;
                int k = u >> 5, c = u & 31;
                float4 v = __ldg(&wt4[u]);
                v.x = __uint_as_float(tf32r(v.x)); v.y = __uint_as_float(tf32r(v.y));
                v.z = __uint_as_float(tf32r(v.z)); v.w = __uint_as_float(tf32r(v.w));
                *(float4*)&hB[k*136 + c*4] = v;
            }
        }
        __syncthreads();

        const int wid = tid >> 5, lane = tid & 31;
        const int g = lane >> 2, t = lane & 3;
        const int stripe = wid >> 1, half = wid & 1;
        const int rw = stripe * 16;

        float acc[8][4];
        #pragma unroll
        for (int n = 0; n < 8; n++)
            #pragma unroll
            for (int j = 0; j < 4; j++) acc[n][j] = 0.f;

        const float* Abase = hA + (rw + g)*132 + t;
        #pragma unroll 4
        for (int kk = 0; kk < 16; kk++) {
            const int k0 = kk*8;
            unsigned a0 = __float_as_uint(Abase[k0]);
            unsigned a1 = __float_as_uint(Abase[k0 + 8*132]);
            unsigned a2 = __float_as_uint(Abase[k0 + 4]);
            unsigned a3 = __float_as_uint(Abase[k0 + 8*132 + 4]);
            const float* B0 = hB + (k0 + t)*136 + g + half*64;
            const float* B1 = B0 + 4*136;
            #pragma unroll
            for (int n = 0; n < 8; n++) {
                unsigned b0 = __float_as_uint(B0[n*8]);
                unsigned b1 = __float_as_uint(B1[n*8]);
                mma8(acc[n], a0, a1, a2, a3, b0, b1);
            }
        }
        __syncthreads();

        {   // stage kf tile into hA (coalesced gather; f_b pre-folded)
            const float4* kf4 = (const float4*)g_kftab;
            #pragma unroll
            for (int i = 0; i < 8; i++) {
                int u = tid + i*512;
                int r = u >> 5, c = u & 31;
                *(float4*)&hA[r*132 + c*4] = __ldg(&kf4[(size_t)s_sk[r]*32 + c]);
            }
        }
        __syncthreads();

        const int rloL = rw + g, rhiL = rloL + 8;
        float pp0 = 0.f, pp1 = 0.f;
        #pragma unroll
        for (int n = 0; n < 8; n++) {
            int c = half*64 + n*8 + 2*t;
            float pw0 = spw[c], pw1 = spw[c+1];
            pp0 += ftanh(acc[n][0] + hA[rloL*132 + c    ]) * pw0
                 + ftanh(acc[n][1] + hA[rloL*132 + c + 1]) * pw1;
            pp1 += ftanh(acc[n][2] + hA[rhiL*132 + c    ]) * pw0
                 + ftanh(acc[n][3] + hA[rhiL*132 + c + 1]) * pw1;
        }
        pp0 += __shfl_xor_sync(0xffffffffu, pp0, 1);
        pp0 += __shfl_xor_sync(0xffffffffu, pp0, 2);
        pp1 += __shfl_xor_sync(0xffffffffu, pp1, 1);
        pp1 += __shfl_xor_sync(0xffffffffu, pp1, 2);
        if (t == 0) {
            sred[rloL*2 + half] = pp0;
            sred[rhiL*2 + half] = pp1;
        }
        __syncthreads();
        if (tid < 128) {
            float pp = sred[tid*2] + sred[tid*2 + 1] + p_b[0];
            int row = row0 + tid;
            int bb = row / L_, tt = row % L_;
            if (tt >= 1) out[bb*(L_-1) + (tt-1)] = fsigmoid(pp);
        }
    }
}

// =====================================================================
extern "C" void kernel_launch(void* const* d_in, const int* in_sizes, int n_in,
                              void* d_out, int out_size)
{
    const int*   skills    = (const int*)  d_in[0];
    const int*   responses = (const int*)  d_in[1];
    const float* k_emb     = (const float*)d_in[2];
    const float* v_emb     = (const float*)d_in[3];
    const float* Mk        = (const float*)d_in[4];
    const float* Mv0       = (const float*)d_in[5];
    const float* e_W       = (const float*)d_in[6];
    const float* e_b       = (const float*)d_in[7];
    const float* a_W       = (const float*)d_in[8];
    const float* a_b       = (const float*)d_in[9];
    const float* f_W       = (const float*)d_in[10];
    const float* f_b       = (const float*)d_in[11];
    const float* p_W       = (const float*)d_in[12];
    const float* p_b       = (const float*)d_in[13];
    float* out = (float*)d_out;

    // phase 2 is the smem high-water mark: 3*L*64 floats = 150KB
    const size_t SZ = (size_t)(3*L_*64) * sizeof(float);   // 153600

    cudaFuncSetAttribute(k_all, cudaFuncAttributeMaxDynamicSharedMemorySize, (int)SZ);
    k_all<<<NBLK, 512, SZ>>>(skills, responses, k_emb, v_emb, Mk, Mv0,
                             e_W, e_b, a_W, a_b, f_W, f_b, p_W, p_b, out);
}

// round 15
// speedup vs baseline: 1.0848x; 1.0848x over previous
#include <cuda_runtime.h>

#define B_  64
#define L_  200
#define NS_ 1000
#define D_  128
#define M_  50
#define BL_ (B_*L_)
#define WSTR 64   // padded w-row stride (slots 50..63 zero)

// -------- scratch (device globals; no allocation allowed) --------
__device__ float g_wtab[1024*WSTR];   // softmax weights per skill (padded)
__device__ float g_etab[2048*D_];     // sigmoid erase per x (rows>=2000 junk)
__device__ float g_atab[2048*D_];     // tanh add per x
__device__ float g_kftab[1024*D_];    // k_emb[s] @ f_Wk^T + f_b
__device__ float g_read[BL_*D_];      // read vectors

__device__ __forceinline__ float fsigmoid(float x){ return 1.f/(1.f+__expf(-x)); }
__device__ __forceinline__ float ftanh(float x){ float y; asm("tanh.approx.f32 %0, %1;":"=f"(y):"f"(x)); return y; }
__device__ __forceinline__ unsigned tf32r(float x){
    unsigned r; asm("cvt.rna.tf32.f32 %0, %1;" : "=r"(r) : "f"(x)); return r;
}
__device__ __forceinline__ void mma8(float* c,
        unsigned a0, unsigned a1, unsigned a2, unsigned a3,
        unsigned b0, unsigned b1){
    asm("mma.sync.aligned.m16n8k8.row.col.f32.tf32.tf32.f32 "
        "{%0,%1,%2,%3}, {%4,%5,%6,%7}, {%8,%9}, {%0,%1,%2,%3};"
        : "+f"(c[0]), "+f"(c[1]), "+f"(c[2]), "+f"(c[3])
        : "r"(a0), "r"(a1), "r"(a2), "r"(a3), "r"(b0), "r"(b1));
}

// =====================================================================
// Kernel A: build all tables. 96 blocks x 512 threads.
//   [0,32)  e-table  (tf32 mma, 64 rows/block)
//   [32,64) a-table  [64,80) kf-table (+f_b)
//   [80,96) w-table  (softmax, FFMA, 64 rows/block)
// Weights staged DIRECTLY from gmem rows into hB[n][132] (row-major,
// pad 132 => B-fragment lane addr mod 32 = 4g+t : conflict-free).
// =====================================================================
extern "C" __global__ void __launch_bounds__(512)
kA_tables(const float* __restrict__ k_emb, const float* __restrict__ v_emb,
          const float* __restrict__ Mk,
          const float* __restrict__ e_W, const float* __restrict__ e_b,
          const float* __restrict__ a_W, const float* __restrict__ a_b,
          const float* __restrict__ f_W, const float* __restrict__ f_b)
{
    extern __shared__ float sm[];
    const int tid = threadIdx.x;
    const int bid = blockIdx.x;

    if (bid < 80) {
        // ------- e/a/kf tables: tf32 mma GEMM, 64 rows/block -------
        float* hA = sm;                  // 64*132 tf32 activations [r][k]
        float* hB = sm + 64*132;         // 128*132 tf32 weights [n][k]
        const int type  = (bid < 32) ? 0 : (bid < 64) ? 1 : 2;
        const int rbase = (type == 0 ? bid : type == 1 ? bid - 32 : bid - 64) * 64;
        const float* xs = (type == 2) ? k_emb : v_emb;
        const float* bv = (type == 0) ? e_b : (type == 1) ? a_b : f_b;
        const int rmax  = (type == 2) ? NS_ - 1 : 2*NS_ - 1;

        {   // stage A (64 gathered rows): 2048 f4
            const float4* xs4 = (const float4*)xs;
            #pragma unroll
            for (int i = 0; i < 4; i++) {
                int u = tid + i*512;
                int r = u >> 5, c = u & 31;
                int rr = min(rbase + r, rmax);
                float4 v = __ldg(&xs4[(size_t)rr*32 + c]);
                v.x = __uint_as_float(tf32r(v.x)); v.y = __uint_as_float(tf32r(v.y));
                v.z = __uint_as_float(tf32r(v.z)); v.w = __uint_as_float(tf32r(v.w));
                *(float4*)&hA[r*132 + c*4] = v;
            }
        }
        {   // stage B rows directly: hB[n*132 + k] = W[n][k]
            #pragma unroll
            for (int i = 0; i < 8; i++) {
                int u = tid + i*512;
                int n = u >> 5, c = u & 31;
                float4 v;
                if (type == 0)      v = __ldg(&((const float4*)e_W)[n*32 + c]);
                else if (type == 1) v = __ldg(&((const float4*)a_W)[n*32 + c]);
                else                v = __ldg(&((const float4*)f_W)[n*64 + 32 + c]); // k-half
                v.x = __uint_as_float(tf32r(v.x)); v.y = __uint_as_float(tf32r(v.y));
                v.z = __uint_as_float(tf32r(v.z)); v.w = __uint_as_float(tf32r(v.w));
                *(float4*)&hB[n*132 + c*4] = v;
            }
        }
        __syncthreads();

        const int wid = tid >> 5, lane = tid & 31;
        const int g = lane >> 2, t = lane & 3;
        const int stripe = wid >> 2, q = wid & 3;
        const int rw = stripe * 16;

        float acc[4][4];
        #pragma unroll
        for (int n = 0; n < 4; n++)
            #pragma unroll
            for (int j = 0; j < 4; j++) acc[n][j] = 0.f;

        const float* Abase = hA + (rw + g)*132 + t;
        const float* Bbase = hB + (q*32 + g)*132 + t;
        #pragma unroll 4
        for (int kk = 0; kk < 16; kk++) {
            const int k0 = kk*8;
            unsigned a0 = __float_as_uint(Abase[k0]);
            unsigned a1 = __float_as_uint(Abase[k0 + 8*132]);
            unsigned a2 = __float_as_uint(Abase[k0 + 4]);
            unsigned a3 = __float_as_uint(Abase[k0 + 8*132 + 4]);
            #pragma unroll
            for (int n = 0; n < 4; n++) {
                unsigned b0 = __float_as_uint(Bbase[n*8*132 + k0]);
                unsigned b1 = __float_as_uint(Bbase[n*8*132 + k0 + 4]);
                mma8(acc[n], a0, a1, a2, a3, b0, b1);
            }
        }

        const int rlo = rbase + rw + g, rhi = rlo + 8;
        #pragma unroll
        for (int n = 0; n < 4; n++) {
            int c = q*32 + n*8 + 2*t;
            float2 bb = *(const float2*)&bv[c];
            float x0 = acc[n][0] + bb.x, x1 = acc[n][1] + bb.y;
            float y0 = acc[n][2] + bb.x, y1 = acc[n][3] + bb.y;
            float2 lo, hi;
            if (type == 0) {
                lo.x = fsigmoid(x0); lo.y = fsigmoid(x1);
                hi.x = fsigmoid(y0); hi.y = fsigmoid(y1);
                *(float2*)&g_etab[(size_t)rlo*D_ + c] = lo;
                *(float2*)&g_etab[(size_t)rhi*D_ + c] = hi;
            } else if (type == 1) {
                lo.x = ftanh(x0); lo.y = ftanh(x1);
                hi.x = ftanh(y0); hi.y = ftanh(y1);
                *(float2*)&g_atab[(size_t)rlo*D_ + c] = lo;
                *(float2*)&g_atab[(size_t)rhi*D_ + c] = hi;
            } else {
                lo.x = x0; lo.y = x1; hi.x = y0; hi.y = y1;
                *(float2*)&g_kftab[(size_t)rlo*D_ + c] = lo;
                *(float2*)&g_kftab[(size_t)rhi*D_ + c] = hi;
            }
        }
    } else {
        // ---------------- w (softmax) table, 64 rows, FFMA ----------------
        float* sx  = sm;                 // 64*128
        float* MkT = sm + 64*D_;         // 128*65 (pad 65: conflict-free)
        const int rbase = (bid - 80) * 64;
        const int tx = tid & 31, ty = tid >> 5;
        const int r0 = ty * 4;

        for (int i = tid; i < M_*D_; i += 512) {
            int m = i >> 7, k = i & 127;
            MkT[k*65 + m] = Mk[i];
        }
        for (int i = tid; i < D_*14; i += 512) {
            int k = i / 14, m = 50 + (i % 14);
            MkT[k*65 + m] = 0.f;
        }
        {
            float4* s4 = (float4*)sx;
            const float4* ke4 = (const float4*)k_emb;
            #pragma unroll
            for (int i = 0; i < 4; i++) {
                int u = tid + i*512;
                int r = u >> 5, cc = u & 31;
                int rr = min(rbase + r, NS_ - 1);
                s4[u] = __ldg(&ke4[(size_t)rr*32 + cc]);
            }
        }
        __syncthreads();

        const int m0 = tx, m1 = tx + 32;
        float a0[4] = {}, a1[4] = {};
        const float4* s4 = (const float4*)sx;
        #pragma unroll 4
        for (int k4 = 0; k4 < 32; k4++) {
            float4 kr[4];
            #pragma unroll
            for (int i = 0; i < 4; i++) kr[i] = s4[(r0+i)*32 + k4];
            #pragma unroll
            for (int s = 0; s < 4; s++) {
                int k = 4*k4 + s;
                float mv0 = MkT[k*65 + m0];
                float mv1 = MkT[k*65 + m1];
                #pragma unroll
                for (int i = 0; i < 4; i++) {
                    float kv = ((const float*)&kr[i])[s];
                    a0[i] = fmaf(kv, mv0, a0[i]);
                    a1[i] = fmaf(kv, mv1, a1[i]);
                }
            }
        }
        #pragma unroll
        for (int i = 0; i < 4; i++) {
            float v0 = a0[i];
            float v1 = (m1 < M_) ? a1[i] : -1e30f;
            float mx = fmaxf(v0, v1);
            #pragma unroll
            for (int o = 16; o >= 1; o >>= 1) mx = fmaxf(mx, __shfl_xor_sync(0xffffffffu, mx, o));
            float e0 = __expf(v0 - mx);
            float e1 = (m1 < M_) ? __expf(v1 - mx) : 0.f;
            float s = e0 + e1;
            #pragma unroll
            for (int o = 16; o >= 1; o >>= 1) s += __shfl_xor_sync(0xffffffffu, s, o);
            float inv = __frcp_rn(s);
            int row = rbase + r0 + i;
            g_wtab[row*WSTR + m0] = e0 * inv;
            g_wtab[row*WSTR + m1] = e1 * inv;   // zero in pad region
        }
    }
}

// =====================================================================
// Kernel B: sequential scan; grid (B, 2 d-halves) x 512 threads.
// Strided m-ownership (7 slots/thread); w/e/a staged to smem up front.
// =====================================================================
extern "C" __global__ void __launch_bounds__(512)
kB_scan(const int* __restrict__ skills, const int* __restrict__ responses,
        const float* __restrict__ Mv0)
{
    extern __shared__ float sb[];
    float* s_w = sb;               // L*64
    float* s_e = sb + L_*64;       // L*64 (this block's 64-d slice)
    float* s_a = sb + 2*L_*64;     // L*64
    __shared__ int s_x[L_], s_sk[L_];

    const int b   = blockIdx.x;
    const int tid = threadIdx.x;
    const int dhalf = blockIdx.y;        // 0 or 1

    for (int t = tid; t < L_; t += 512) {
        int sk = skills[b*L_ + t];
        int r  = responses[b*L_ + t];
        int mr = (r > -1) ? r : 0;
        s_sk[t] = sk;
        s_x[t]  = sk + NS_ * mr;
    }
    __syncthreads();

    {   // bulk stage: 16 float4 per t per table
        float4* sw4 = (float4*)s_w;
        float4* se4 = (float4*)s_e;
        float4* sa4 = (float4*)s_a;
        const float4* wt4 = (const float4*)g_wtab;
        const float4* et4 = (const float4*)g_etab;
        const float4* at4 = (const float4*)g_atab;
        const int dbase4 = dhalf * 16;
        for (int u = tid; u < L_*16; u += 512) {
            int t = u >> 4, c = u & 15;
            int xx = s_x[t], kk = s_sk[t];
            sw4[u] = __ldg(&wt4[kk*16 + c]);
            se4[u] = __ldg(&et4[(size_t)xx*32 + dbase4 + c]);
            sa4[u] = __ldg(&at4[(size_t)xx*32 + dbase4 + c]);
        }
    }
    __syncthreads();

    const int mg  = tid & 7;
    const int dl  = tid >> 3;
    const int d   = dhalf * 64 + dl;

    float mv[7];
    #pragma unroll
    for (int j = 0; j < 7; j++) {
        int m = mg + 8*j;
        mv[j] = (m < M_) ? Mv0[m*D_ + d] : 0.f;
    }

    float* rp = g_read + (size_t)b*L_*D_ + d;

    #pragma unroll 2
    for (int t = 0; t < L_; t++) {
        float ev = s_e[t*64 + dl];
        float av = s_a[t*64 + dl];
        const float* wrow = &s_w[t*64 + mg];

        float rda = 0.f, rdb = 0.f;
        #pragma unroll
        for (int j = 0; j < 7; j++) {
            float w = wrow[8*j];                 // broadcast-friendly scalar LDS
            float r_ = fmaf(w, mv[j], 0.f);
            if (j & 1) rdb += r_; else rda += r_;
            float g = fmaf(-ev, mv[j], av);      // a - e*mv
            mv[j] = fmaf(w, g, mv[j]);           // mv += w*(a - e*mv)
        }
        float rd = rda + rdb;
        rd += __shfl_xor_sync(0xffffffffu, rd, 1);
        rd += __shfl_xor_sync(0xffffffffu, rd, 2);
        rd += __shfl_xor_sync(0xffffffffu, rd, 4);
        if (mg == 0) rp[t*D_] = rd;
    }
}

// =====================================================================
// Kernel C: tf32 mma GEMM + fused epilogue. 100 blocks x 512 threads,
// 128 rows/block (R12 proven shape). B = f_W read-half rows staged
// directly into hB[n][132] (row-major, conflict-free fragment reads).
// =====================================================================
extern "C" __global__ void __launch_bounds__(512)
kC_out(const int* __restrict__ skills, const float* __restrict__ f_W,
       const float* __restrict__ p_W, const float* __restrict__ p_b,
       float* __restrict__ out)
{
    extern __shared__ float sm[];
    float* hA   = sm;                       // 128*132 (A tf32, later kf tile)
    float* hB   = sm + 128*132;             // 128*132 (f_W read-half, [n][k])
    float* spw  = sm + 128*132 + 128*132;   // 128 (p_W)
    float* sred = spw + 128;                // 256 (row x half partials)
    __shared__ int s_sk[128];

    const int tid  = threadIdx.x;
    const int row0 = blockIdx.x * 128;

    if (tid < 128) { s_sk[tid] = skills[row0 + tid]; spw[tid] = p_W[tid]; }
    {   // stage A
        const float4* rd4 = (const float4*)g_read;
        #pragma unroll
        for (int i = 0; i < 8; i++) {
            int u = tid + i*512;
            int r = u >> 5, c = u & 31;
            float4 v = __ldg(&rd4[(size_t)row0*32 + u]);
            v.x = __uint_as_float(tf32r(v.x)); v.y = __uint_as_float(tf32r(v.y));
            v.z = __uint_as_float(tf32r(v.z)); v.w = __uint_as_float(tf32r(v.w));
            *(float4*)&hA[r*132 + c*4] = v;
        }
    }
    {   // stage B: f_W rows, read half (first 128 cols of 256)
        const float4* fw4 = (const float4*)f_W;
        #pragma unroll
        for (int i = 0; i < 8; i++) {
            int u = tid + i*512;
            int n = u >> 5, c = u & 31;
            float4 v = __ldg(&fw4[n*64 + c]);
            v.x = __uint_as_float(tf32r(v.x)); v.y = __uint_as_float(tf32r(v.y));
            v.z = __uint_as_float(tf32r(v.z)); v.w = __uint_as_float(tf32r(v.w));
            *(float4*)&hB[n*132 + c*4] = v;
        }
    }
    __syncthreads();

    const int wid = tid >> 5, lane = tid & 31;
    const int g = lane >> 2, t = lane & 3;
    const int stripe = wid >> 1, half = wid & 1;
    const int rw = stripe * 16;

    float acc[8][4];
    #pragma unroll
    for (int n = 0; n < 8; n++)
        #pragma unroll
        for (int j = 0; j < 4; j++) acc[n][j] = 0.f;

    const float* Abase = hA + (rw + g)*132 + t;
    const float* Bbase = hB + (half*64 + g)*132 + t;
    #pragma unroll 4
    for (int kk = 0; kk < 16; kk++) {
        const int k0 = kk*8;
        unsigned a0 = __float_as_uint(Abase[k0]);
        unsigned a1 = __float_as_uint(Abase[k0 + 8*132]);
        unsigned a2 = __float_as_uint(Abase[k0 + 4]);
        unsigned a3 = __float_as_uint(Abase[k0 + 8*132 + 4]);
        #pragma unroll
        for (int n = 0; n < 8; n++) {
            unsigned b0 = __float_as_uint(Bbase[n*8*132 + k0]);
            unsigned b1 = __float_as_uint(Bbase[n*8*132 + k0 + 4]);
            mma8(acc[n], a0, a1, a2, a3, b0, b1);
        }
    }
    __syncthreads();                       // all mma reads of hA done

    {   // stage kf tile into hA (coalesced gather; f_b pre-folded)
        const float4* kf4 = (const float4*)g_kftab;
        #pragma unroll
        for (int i = 0; i < 8; i++) {
            int u = tid + i*512;
            int r = u >> 5, c = u & 31;
            *(float4*)&hA[r*132 + c*4] = __ldg(&kf4[(size_t)s_sk[r]*32 + c]);
        }
    }
    __syncthreads();

    const int rloL = rw + g, rhiL = rloL + 8;
    float pp0 = 0.f, pp1 = 0.f;
    #pragma unroll
    for (int n = 0; n < 8; n++) {
        int c = half*64 + n*8 + 2*t;
        float pw0 = spw[c], pw1 = spw[c+1];
        pp0 += ftanh(acc[n][0] + hA[rloL*132 + c    ]) * pw0
             + ftanh(acc[n][1] + hA[rloL*132 + c + 1]) * pw1;
        pp1 += ftanh(acc[n][2] + hA[rhiL*132 + c    ]) * pw0
             + ftanh(acc[n][3] + hA[rhiL*132 + c + 1]) * pw1;
    }
    pp0 += __shfl_xor_sync(0xffffffffu, pp0, 1);
    pp0 += __shfl_xor_sync(0xffffffffu, pp0, 2);
    pp1 += __shfl_xor_sync(0xffffffffu, pp1, 1);
    pp1 += __shfl_xor_sync(0xffffffffu, pp1, 2);
    if (t == 0) {
        sred[rloL*2 + half] = pp0;
        sred[rhiL*2 + half] = pp1;
    }
    __syncthreads();
    if (tid < 128) {
        float pp = sred[tid*2] + sred[tid*2 + 1] + p_b[0];
        int row = row0 + tid;
        int bb = row / L_, tt = row % L_;
        if (tt >= 1) out[bb*(L_-1) + (tt-1)] = fsigmoid(pp);
    }
}

// =====================================================================
extern "C" void kernel_launch(void* const* d_in, const int* in_sizes, int n_in,
                              void* d_out, int out_size)
{
    const int*   skills    = (const int*)  d_in[0];
    const int*   responses = (const int*)  d_in[1];
    const float* k_emb     = (const float*)d_in[2];
    const float* v_emb     = (const float*)d_in[3];
    const float* Mk        = (const float*)d_in[4];
    const float* Mv0       = (const float*)d_in[5];
    const float* e_W       = (const float*)d_in[6];
    const float* e_b       = (const float*)d_in[7];
    const float* a_W       = (const float*)d_in[8];
    const float* a_b       = (const float*)d_in[9];
    const float* f_W       = (const float*)d_in[10];
    const float* f_b       = (const float*)d_in[11];
    const float* p_W       = (const float*)d_in[12];
    const float* p_b       = (const float*)d_in[13];
    float* out = (float*)d_out;

    const size_t SZA = (size_t)(64*132 + 128*132) * sizeof(float);              // 101376
    const size_t SZB = (size_t)(3*L_*64) * sizeof(float);                       // 153600
    const size_t SZC = (size_t)(128*132 + 128*132 + 128 + 256) * sizeof(float); // 136704

    cudaFuncSetAttribute(kA_tables, cudaFuncAttributeMaxDynamicSharedMemorySize, (int)SZA);
    cudaFuncSetAttribute(kB_scan,   cudaFuncAttributeMaxDynamicSharedMemorySize, (int)SZB);
    cudaFuncSetAttribute(kC_out,    cudaFuncAttributeMaxDynamicSharedMemorySize, (int)SZC);

    kA_tables<<<96, 512, SZA>>>(k_emb, v_emb, Mk, e_W, e_b, a_W, a_b, f_W, f_b);
    kB_scan<<<dim3(B_, 2), 512, SZB>>>(skills, responses, Mv0);
    kC_out<<<100, 512, SZC>>>(skills, f_W, p_W, p_b, out);
}